// round 5
// baseline (speedup 1.0000x reference)
#include <cuda_runtime.h>
#include <cuda_bf16.h>
#include <mma.h>

using namespace nvcuda;

#define B_      2
#define L_      2048
#define DMODEL  1024
#define DINNER  2048
#define DSTATE  16
#define DTRANK  64
#define M_      (B_ * L_)          // 4096
#define NCHUNK  16
#define CHUNK   (L_ / NCHUNK)      // 128

// ---------------- fp32 scratch ----------------
__device__ float g_xz[(size_t)M_ * 4096];        // [m][0:2048)=x, [2048:4096)=z
__device__ float g_xconv[(size_t)M_ * DINNER];
__device__ float g_proj[(size_t)M_ * 128];       // 0:64 dt_low, 64:80 B, 80:96 C
__device__ float g_dt[(size_t)M_ * DINNER];
__device__ float g_cP[(size_t)B_ * NCHUNK * DSTATE * DINNER];
__device__ float g_cH[(size_t)B_ * NCHUNK * DSTATE * DINNER];
__device__ float g_cH0[(size_t)B_ * NCHUNK * DSTATE * DINNER];

// ---------------- planar split-bf16 scratch (hi/lo) ----------------
__device__ __nv_bfloat16 g_hs_h[(size_t)M_ * DMODEL],  g_hs_l[(size_t)M_ * DMODEL];
__device__ __nv_bfloat16 g_win_h[(size_t)DMODEL * 4096], g_win_l[(size_t)DMODEL * 4096];
__device__ __nv_bfloat16 g_wx_h[(size_t)DINNER * 128],  g_wx_l[(size_t)DINNER * 128];   // padded 96->128
__device__ __nv_bfloat16 g_wdt_h[(size_t)DTRANK * DINNER], g_wdt_l[(size_t)DTRANK * DINNER];
__device__ __nv_bfloat16 g_wout_h[(size_t)DINNER * DMODEL], g_wout_l[(size_t)DINNER * DMODEL];
__device__ __nv_bfloat16 g_xc_h[(size_t)M_ * DINNER],  g_xc_l[(size_t)M_ * DINNER];
__device__ __nv_bfloat16 g_pj_h[(size_t)M_ * 128],     g_pj_l[(size_t)M_ * 128];
__device__ __nv_bfloat16 g_y_h[(size_t)M_ * DINNER],   g_y_l[(size_t)M_ * DINNER];

// ---------------- generic fp32 -> (hi,lo) bf16 planar ----------------
__global__ void cvt_planar(const float* __restrict__ src,
                           __nv_bfloat16* __restrict__ h,
                           __nv_bfloat16* __restrict__ l, int n)
{
    int i = blockIdx.x * blockDim.x + threadIdx.x;
    if (i < n) {
        float v = src[i];
        __nv_bfloat16 hh = __float2bfloat16(v);
        h[i] = hh;
        l[i] = __float2bfloat16(v - __bfloat162float(hh));
    }
}

// W_x: 2048 x 96 -> planar 2048 x 128 (zero-pad cols 96..127)
__global__ void cvt_wx(const float* __restrict__ src)
{
    int i = blockIdx.x * blockDim.x + threadIdx.x;   // 2048*128
    int r = i >> 7, c = i & 127;
    float v = (c < 96) ? src[r * 96 + c] : 0.0f;
    __nv_bfloat16 hh = __float2bfloat16(v);
    g_wx_h[i] = hh;
    g_wx_l[i] = __float2bfloat16(v - __bfloat162float(hh));
}

// ---------------- planar split-bf16 GEMM, cp.async 3-stage pipeline ----------------
#define GBM 128
#define GBN 128
#define GBK 32
#define NSTG 3
#define ALD 40           // 32 + 8 pad (row stride 80B, 16B-aligned)
#define BLD 136          // 128 + 8 pad (row stride 272B, 16B-aligned)
#define A_ELEMS (GBM * ALD)                 // 5120
#define B_ELEMS (GBK * BLD)                 // 4352
#define STAGE_ELEMS (2 * A_ELEMS + 2 * B_ELEMS)   // 18944
#define GEMM_SMEM_BYTES (NSTG * STAGE_ELEMS * 2)  // 113664

__device__ __forceinline__ void cpa16(__nv_bfloat16* dst, const __nv_bfloat16* src)
{
    unsigned d = (unsigned)__cvta_generic_to_shared(dst);
    asm volatile("cp.async.cg.shared.global [%0], [%1], 16;\n" :: "r"(d), "l"(src));
}
#define CP_COMMIT() asm volatile("cp.async.commit_group;\n" ::: "memory")
#define CP_WAIT(N)  asm volatile("cp.async.wait_group %0;\n" :: "n"(N) : "memory")

__global__ __launch_bounds__(256) void gemm_planar(
    const __nv_bfloat16* __restrict__ Agh, const __nv_bfloat16* __restrict__ Agl, int lda,
    const __nv_bfloat16* __restrict__ Bgh, const __nv_bfloat16* __restrict__ Bgl, int ldb,
    float* __restrict__ C, int ldc, int ktiles)
{
    extern __shared__ __nv_bfloat16 sm[];
    const int tid = threadIdx.x;
    const int m0 = blockIdx.y * GBM, n0 = blockIdx.x * GBN;
    const int wid = tid >> 5;
    const int wm = wid >> 2;      // 0..1 : 64 rows each
    const int wn = wid & 3;       // 0..3 : 32 cols each

    wmma::fragment<wmma::accumulator, 16, 16, 16, float> acc[4][2];
    #pragma unroll
    for (int i = 0; i < 4; i++)
        #pragma unroll
        for (int j = 0; j < 2; j++) wmma::fill_fragment(acc[i][j], 0.0f);

    auto load_stage = [&](int kt, int s) {
        __nv_bfloat16* base = sm + s * STAGE_ELEMS;
        __nv_bfloat16* sAh = base;
        __nv_bfloat16* sAl = base + A_ELEMS;
        __nv_bfloat16* sBh = base + 2 * A_ELEMS;
        __nv_bfloat16* sBl = base + 2 * A_ELEMS + B_ELEMS;
        int k0 = kt * GBK;
        // A tile: 128 rows x 32 cols, hi+lo. 512 16B-chunks per plane.
        #pragma unroll
        for (int p = 0; p < 2; p++) {
            int idx = tid + p * 256;        // 0..511
            int r = idx >> 2, cc = (idx & 3) * 8;
            size_t goff = (size_t)(m0 + r) * lda + k0 + cc;
            cpa16(sAh + r * ALD + cc, Agh + goff);
            cpa16(sAl + r * ALD + cc, Agl + goff);
        }
        // B tile: 32 rows x 128 cols, hi+lo. 512 16B-chunks per plane.
        #pragma unroll
        for (int p = 0; p < 2; p++) {
            int idx = tid + p * 256;        // 0..511
            int r = idx >> 4, cc = (idx & 15) * 8;
            size_t goff = (size_t)(k0 + r) * ldb + n0 + cc;
            cpa16(sBh + r * BLD + cc, Bgh + goff);
            cpa16(sBl + r * BLD + cc, Bgl + goff);
        }
        CP_COMMIT();
    };

    auto compute_stage = [&](int s) {
        __nv_bfloat16* base = sm + s * STAGE_ELEMS;
        __nv_bfloat16* sAh = base;
        __nv_bfloat16* sAl = base + A_ELEMS;
        __nv_bfloat16* sBh = base + 2 * A_ELEMS;
        __nv_bfloat16* sBl = base + 2 * A_ELEMS + B_ELEMS;
        #pragma unroll
        for (int kk = 0; kk < GBK; kk += 16) {
            wmma::fragment<wmma::matrix_a, 16, 16, 16, __nv_bfloat16, wmma::row_major> ah[4], al[4];
            wmma::fragment<wmma::matrix_b, 16, 16, 16, __nv_bfloat16, wmma::row_major> bh[2], bl[2];
            #pragma unroll
            for (int i = 0; i < 4; i++) {
                wmma::load_matrix_sync(ah[i], sAh + (wm * 64 + i * 16) * ALD + kk, ALD);
                wmma::load_matrix_sync(al[i], sAl + (wm * 64 + i * 16) * ALD + kk, ALD);
            }
            #pragma unroll
            for (int j = 0; j < 2; j++) {
                wmma::load_matrix_sync(bh[j], sBh + kk * BLD + wn * 32 + j * 16, BLD);
                wmma::load_matrix_sync(bl[j], sBl + kk * BLD + wn * 32 + j * 16, BLD);
            }
            #pragma unroll
            for (int i = 0; i < 4; i++)
                #pragma unroll
                for (int j = 0; j < 2; j++) {
                    wmma::mma_sync(acc[i][j], ah[i], bh[j], acc[i][j]);
                    wmma::mma_sync(acc[i][j], ah[i], bl[j], acc[i][j]);
                    wmma::mma_sync(acc[i][j], al[i], bh[j], acc[i][j]);
                }
        }
    };

    // prologue: fill up to 3 stages
    load_stage(0, 0);
    if (ktiles > 1) load_stage(1, 1);
    if (ktiles > 2) load_stage(2, 2);

    for (int kt = 0; kt < ktiles; kt++) {
        int rem = ktiles - 1 - kt;          // loads that may still be pending beyond kt
        if (rem >= 2)      { CP_WAIT(2); }
        else if (rem == 1) { CP_WAIT(1); }
        else               { CP_WAIT(0); }
        __syncthreads();

        int s = kt % NSTG;
        compute_stage(s);
        __syncthreads();

        if (kt + NSTG < ktiles) load_stage(kt + NSTG, s);
    }

    #pragma unroll
    for (int i = 0; i < 4; i++)
        #pragma unroll
        for (int j = 0; j < 2; j++) {
            int gm = m0 + wm * 64 + i * 16;
            int gn = n0 + wn * 32 + j * 16;
            wmma::store_matrix_sync(&C[(size_t)gm * ldc + gn], acc[i][j], ldc, wmma::mem_row_major);
        }
}

// ---------------- depthwise causal conv(4) + SiLU (+ planar out) ----------------
__global__ void conv_silu_kernel(const float* __restrict__ cw,
                                 const float* __restrict__ cb)
{
    int idx = blockIdx.x * blockDim.x + threadIdx.x;   // over M_*DINNER
    int d = idx & (DINNER - 1);
    int m = idx >> 11;
    int l = m & (L_ - 1);
    int b = m >> 11;
    float acc = cb[d];
    #pragma unroll
    for (int w = 0; w < 4; w++) {
        int ll = l - 3 + w;
        if (ll >= 0)
            acc += g_xz[((size_t)(b * L_ + ll)) * 4096 + d] * cw[w * DINNER + d];
    }
    float v = acc / (1.0f + __expf(-acc));
    g_xconv[idx] = v;
    __nv_bfloat16 hh = __float2bfloat16(v);
    g_xc_h[idx] = hh;
    g_xc_l[idx] = __float2bfloat16(v - __bfloat162float(hh));
}

// ---------------- dt = softplus(dt_pre + b_dt) ----------------
__global__ void dt_softplus_kernel(const float* __restrict__ bdt)
{
    int idx = blockIdx.x * blockDim.x + threadIdx.x;
    int d = idx & (DINNER - 1);
    float v = g_dt[idx] + bdt[d];
    g_dt[idx] = (v > 20.0f) ? v : log1pf(__expf(v));
}

// ---------------- selective scan pass 1 ----------------
__global__ __launch_bounds__(256) void scan_pass1(const float* __restrict__ A_log)
{
    __shared__ float sBC[CHUNK][32];
    const int d = blockIdx.x * 256 + threadIdx.x;
    const int c = blockIdx.y;
    const int b = blockIdx.z;

    for (int i = threadIdx.x; i < CHUNK * 32; i += 256) {
        int r = i >> 5, q = i & 31;
        sBC[r][q] = g_proj[(size_t)(b * L_ + c * CHUNK + r) * 128 + 64 + q];
    }
    __syncthreads();

    float ac[DSTATE], P[DSTATE], h[DSTATE];
    #pragma unroll
    for (int s = 0; s < DSTATE; s++) {
        ac[s] = -expf(A_log[d * DSTATE + s]);
        P[s] = 1.0f;
        h[s] = 0.0f;
    }

    size_t base = (size_t)(b * L_ + c * CHUNK) * DINNER + d;
    for (int t = 0; t < CHUNK; t++) {
        float dtv = g_dt[base + (size_t)t * DINNER];
        float xv  = g_xconv[base + (size_t)t * DINNER];
        float dtx = dtv * xv;
        #pragma unroll
        for (int s = 0; s < DSTATE; s++) {
            float a = __expf(dtv * ac[s]);
            P[s] *= a;
            h[s] = a * h[s] + dtx * sBC[t][s];
        }
    }
    size_t o = ((size_t)(b * NCHUNK + c) * DSTATE) * DINNER + d;
    #pragma unroll
    for (int s = 0; s < DSTATE; s++) {
        g_cP[o + (size_t)s * DINNER] = P[s];
        g_cH[o + (size_t)s * DINNER] = h[s];
    }
}

// ---------------- pass 2: combine chunk states ----------------
__global__ void scan_pass2()
{
    int id = blockIdx.x * blockDim.x + threadIdx.x;    // B_*DINNER
    int b = id >> 11, d = id & (DINNER - 1);
    float h[DSTATE];
    #pragma unroll
    for (int s = 0; s < DSTATE; s++) h[s] = 0.0f;
    for (int c = 0; c < NCHUNK; c++) {
        size_t o = ((size_t)(b * NCHUNK + c) * DSTATE) * DINNER + d;
        #pragma unroll
        for (int s = 0; s < DSTATE; s++) {
            g_cH0[o + (size_t)s * DINNER] = h[s];
            h[s] = g_cP[o + (size_t)s * DINNER] * h[s] + g_cH[o + (size_t)s * DINNER];
        }
    }
}

// ---------------- pass 3: replay with true h0, emit y planes ----------------
__global__ __launch_bounds__(256) void scan_pass3(const float* __restrict__ A_log,
                                                  const float* __restrict__ Dvec)
{
    __shared__ float sBC[CHUNK][32];
    const int d = blockIdx.x * 256 + threadIdx.x;
    const int c = blockIdx.y;
    const int b = blockIdx.z;

    for (int i = threadIdx.x; i < CHUNK * 32; i += 256) {
        int r = i >> 5, q = i & 31;
        sBC[r][q] = g_proj[(size_t)(b * L_ + c * CHUNK + r) * 128 + 64 + q];
    }
    __syncthreads();

    float ac[DSTATE], h[DSTATE];
    size_t o = ((size_t)(b * NCHUNK + c) * DSTATE) * DINNER + d;
    #pragma unroll
    for (int s = 0; s < DSTATE; s++) {
        ac[s] = -expf(A_log[d * DSTATE + s]);
        h[s] = g_cH0[o + (size_t)s * DINNER];
    }
    float Dv = Dvec[d];

    size_t base = (size_t)(b * L_ + c * CHUNK) * DINNER + d;
    for (int t = 0; t < CHUNK; t++) {
        float dtv = g_dt[base + (size_t)t * DINNER];
        float xv  = g_xconv[base + (size_t)t * DINNER];
        float dtx = dtv * xv;
        float acc = 0.0f;
        #pragma unroll
        for (int s = 0; s < DSTATE; s++) {
            float a = __expf(dtv * ac[s]);
            h[s] = a * h[s] + dtx * sBC[t][s];
            acc += h[s] * sBC[t][16 + s];
        }
        acc += xv * Dv;
        float zv = g_xz[(size_t)(b * L_ + c * CHUNK + t) * 4096 + 2048 + d];
        acc *= zv / (1.0f + __expf(-zv));
        size_t oi = base + (size_t)t * DINNER;
        __nv_bfloat16 hh = __float2bfloat16(acc);
        g_y_h[oi] = hh;
        g_y_l[oi] = __float2bfloat16(acc - __bfloat162float(hh));
    }
}

// ---------------- launch ----------------
extern "C" void kernel_launch(void* const* d_in, const int* in_sizes, int n_in,
                              void* d_out, int out_size)
{
    const float* hs     = (const float*)d_in[0];
    const float* W_in   = (const float*)d_in[1];
    const float* conv_w = (const float*)d_in[2];
    const float* conv_b = (const float*)d_in[3];
    const float* W_x    = (const float*)d_in[4];
    const float* W_dt   = (const float*)d_in[5];
    const float* b_dt   = (const float*)d_in[6];
    const float* A_log  = (const float*)d_in[7];
    const float* Dvec   = (const float*)d_in[8];
    const float* W_out  = (const float*)d_in[9];
    float* out = (float*)d_out;

    cudaFuncSetAttribute(gemm_planar, cudaFuncAttributeMaxDynamicSharedMemorySize,
                         GEMM_SMEM_BYTES);

    float *xz, *proj, *dtb;
    __nv_bfloat16 *hs_h, *hs_l, *win_h, *win_l, *wdt_h, *wdt_l, *wout_h, *wout_l;
    __nv_bfloat16 *wx_h, *wx_l, *xc_h, *xc_l, *pj_h, *pj_l, *y_h, *y_l;
    cudaGetSymbolAddress((void**)&xz,    g_xz);
    cudaGetSymbolAddress((void**)&proj,  g_proj);
    cudaGetSymbolAddress((void**)&dtb,   g_dt);
    cudaGetSymbolAddress((void**)&hs_h,  g_hs_h);   cudaGetSymbolAddress((void**)&hs_l,  g_hs_l);
    cudaGetSymbolAddress((void**)&win_h, g_win_h);  cudaGetSymbolAddress((void**)&win_l, g_win_l);
    cudaGetSymbolAddress((void**)&wx_h,  g_wx_h);   cudaGetSymbolAddress((void**)&wx_l,  g_wx_l);
    cudaGetSymbolAddress((void**)&wdt_h, g_wdt_h);  cudaGetSymbolAddress((void**)&wdt_l, g_wdt_l);
    cudaGetSymbolAddress((void**)&wout_h,g_wout_h); cudaGetSymbolAddress((void**)&wout_l,g_wout_l);
    cudaGetSymbolAddress((void**)&xc_h,  g_xc_h);   cudaGetSymbolAddress((void**)&xc_l,  g_xc_l);
    cudaGetSymbolAddress((void**)&pj_h,  g_pj_h);   cudaGetSymbolAddress((void**)&pj_l,  g_pj_l);
    cudaGetSymbolAddress((void**)&y_h,   g_y_h);    cudaGetSymbolAddress((void**)&y_l,   g_y_l);

    // 0) conversions of external inputs (5 launches; launch #6 = big GEMM for ncu -s 5)
    cvt_planar<<<(M_ * DMODEL) / 256, 256>>>(hs, hs_h, hs_l, M_ * DMODEL);
    cvt_planar<<<(DMODEL * 4096) / 256, 256>>>(W_in, win_h, win_l, DMODEL * 4096);
    cvt_wx<<<(DINNER * 128) / 256, 256>>>(W_x);
    cvt_planar<<<(DTRANK * DINNER) / 256, 256>>>(W_dt, wdt_h, wdt_l, DTRANK * DINNER);
    cvt_planar<<<(DINNER * DMODEL) / 256, 256>>>(W_out, wout_h, wout_l, DINNER * DMODEL);

    // 1) xz = hs @ W_in   (4096 x 4096 x 1024)
    gemm_planar<<<dim3(4096 / GBN, M_ / GBM), 256, GEMM_SMEM_BYTES>>>(
        hs_h, hs_l, DMODEL, win_h, win_l, 4096, xz, 4096, DMODEL / GBK);

    // 2) depthwise conv + SiLU (+ planes)
    conv_silu_kernel<<<(M_ * DINNER) / 256, 256>>>(conv_w, conv_b);

    // 3) proj = xconv @ W_x_padded   (4096 x 128 x 2048)
    gemm_planar<<<dim3(1, M_ / GBM), 256, GEMM_SMEM_BYTES>>>(
        xc_h, xc_l, DINNER, wx_h, wx_l, 128, proj, 128, DINNER / GBK);

    // 3b) planar-ize proj (dt_low cols used as GEMM A)
    cvt_planar<<<(M_ * 128) / 256, 256>>>(proj, pj_h, pj_l, M_ * 128);

    // 4) dt_pre = proj[:, :64] @ W_dt   (4096 x 2048 x 64)
    gemm_planar<<<dim3(DINNER / GBN, M_ / GBM), 256, GEMM_SMEM_BYTES>>>(
        pj_h, pj_l, 128, wdt_h, wdt_l, DINNER, dtb, DINNER, DTRANK / GBK);

    // 5) dt = softplus(dt_pre + b_dt)
    dt_softplus_kernel<<<(M_ * DINNER) / 256, 256>>>(b_dt);

    // 6) selective scan (chunked parallel linear recurrence)
    scan_pass1<<<dim3(DINNER / 256, NCHUNK, B_), 256>>>(A_log);
    scan_pass2<<<(B_ * DINNER) / 256, 256>>>();
    scan_pass3<<<dim3(DINNER / 256, NCHUNK, B_), 256>>>(A_log, Dvec);

    // 7) out = y @ W_out   (4096 x 1024 x 2048)
    gemm_planar<<<dim3(DMODEL / GBN, M_ / GBM), 256, GEMM_SMEM_BYTES>>>(
        y_h, y_l, DINNER, wout_h, wout_l, DMODEL, out, DMODEL, DINNER / GBK);
}

// round 6
// speedup vs baseline: 1.0784x; 1.0784x over previous
#include <cuda_runtime.h>
#include <cuda_bf16.h>
#include <mma.h>

using namespace nvcuda;

#define B_      2
#define L_      2048
#define DMODEL  1024
#define DINNER  2048
#define DSTATE  16
#define DTRANK  64
#define M_      (B_ * L_)          // 4096
#define NCHUNK  16
#define CHUNK   (L_ / NCHUNK)      // 128
#define KSLICE  8

// ---------------- fp32 scratch ----------------
__device__ float g_xz[(size_t)M_ * 4096];        // [m][0:2048)=x, [2048:4096)=z
__device__ float g_xconv[(size_t)M_ * DINNER];
__device__ float g_proj[(size_t)M_ * 128];       // 0:64 dt_low, 64:80 B, 80:96 C
__device__ float g_pk[(size_t)KSLICE * M_ * 128]; // split-K partials for proj
__device__ float g_dt[(size_t)M_ * DINNER];
__device__ float g_cP[(size_t)B_ * NCHUNK * DSTATE * DINNER];
__device__ float g_cH[(size_t)B_ * NCHUNK * DSTATE * DINNER];
__device__ float g_cH0[(size_t)B_ * NCHUNK * DSTATE * DINNER];

// ---------------- planar split-bf16 scratch (hi/lo) ----------------
__device__ __nv_bfloat16 g_hs_h[(size_t)M_ * DMODEL],  g_hs_l[(size_t)M_ * DMODEL];
__device__ __nv_bfloat16 g_win_h[(size_t)DMODEL * 4096], g_win_l[(size_t)DMODEL * 4096];
__device__ __nv_bfloat16 g_wx_h[(size_t)DINNER * 128],  g_wx_l[(size_t)DINNER * 128];   // padded 96->128
__device__ __nv_bfloat16 g_wdt_h[(size_t)DTRANK * DINNER], g_wdt_l[(size_t)DTRANK * DINNER];
__device__ __nv_bfloat16 g_wout_h[(size_t)DINNER * DMODEL], g_wout_l[(size_t)DINNER * DMODEL];
__device__ __nv_bfloat16 g_xc_h[(size_t)M_ * DINNER],  g_xc_l[(size_t)M_ * DINNER];
__device__ __nv_bfloat16 g_pj_h[(size_t)M_ * 128],     g_pj_l[(size_t)M_ * 128];
__device__ __nv_bfloat16 g_y_h[(size_t)M_ * DINNER],   g_y_l[(size_t)M_ * DINNER];

// ---------------- generic fp32 -> (hi,lo) bf16 planar ----------------
__global__ void cvt_planar(const float* __restrict__ src,
                           __nv_bfloat16* __restrict__ h,
                           __nv_bfloat16* __restrict__ l, int n)
{
    int i = blockIdx.x * blockDim.x + threadIdx.x;
    if (i < n) {
        float v = src[i];
        __nv_bfloat16 hh = __float2bfloat16(v);
        h[i] = hh;
        l[i] = __float2bfloat16(v - __bfloat162float(hh));
    }
}

// W_x: 2048 x 96 -> planar 2048 x 128 (zero-pad cols 96..127)
__global__ void cvt_wx(const float* __restrict__ src)
{
    int i = blockIdx.x * blockDim.x + threadIdx.x;   // 2048*128
    int r = i >> 7, c = i & 127;
    float v = (c < 96) ? src[r * 96 + c] : 0.0f;
    __nv_bfloat16 hh = __float2bfloat16(v);
    g_wx_h[i] = hh;
    g_wx_l[i] = __float2bfloat16(v - __bfloat162float(hh));
}

// reduce split-K partials into g_proj
__global__ void reduce_proj()
{
    int i = blockIdx.x * blockDim.x + threadIdx.x;   // M_*128
    float s = 0.0f;
    #pragma unroll
    for (int z = 0; z < KSLICE; z++)
        s += g_pk[(size_t)z * M_ * 128 + i];
    g_proj[i] = s;
}

// ---------------- planar split-bf16 GEMM ----------------
// CTA tile 256x128, warp tile 64x64 (8 warps, 4M x 2N), 2-stage cp.async.
#define GBM 256
#define GBN 128
#define GBK 32
#define ALD 40           // 32 + 8 pad
#define BLD 136          // 128 + 8 pad
#define A_ELEMS (GBM * ALD)                 // 10240
#define B_ELEMS (GBK * BLD)                 // 4352
#define STAGE_ELEMS (2 * A_ELEMS + 2 * B_ELEMS)   // 29184
#define GEMM_SMEM_BYTES (2 * STAGE_ELEMS * 2)     // 116736

__device__ __forceinline__ void cpa16(__nv_bfloat16* dst, const __nv_bfloat16* src)
{
    unsigned d = (unsigned)__cvta_generic_to_shared(dst);
    asm volatile("cp.async.cg.shared.global [%0], [%1], 16;\n" :: "r"(d), "l"(src));
}
#define CP_COMMIT() asm volatile("cp.async.commit_group;\n" ::: "memory")
#define CP_WAIT(N)  asm volatile("cp.async.wait_group %0;\n" :: "n"(N) : "memory")

__global__ __launch_bounds__(256) void gemm_planar(
    const __nv_bfloat16* __restrict__ Agh, const __nv_bfloat16* __restrict__ Agl, int lda,
    const __nv_bfloat16* __restrict__ Bgh, const __nv_bfloat16* __restrict__ Bgl, int ldb,
    float* __restrict__ C, int ldc, int ktiles, size_t slice_stride)
{
    extern __shared__ __nv_bfloat16 sm[];
    const int tid = threadIdx.x;
    const int m0 = blockIdx.y * GBM, n0 = blockIdx.x * GBN;
    const int kbase = blockIdx.z * ktiles;           // chunk offset for split-K
    float* Cz = C + (size_t)blockIdx.z * slice_stride;
    const int wid = tid >> 5;
    const int wm = wid >> 1;      // 0..3 : 64 rows each
    const int wn = wid & 1;       // 0..1 : 64 cols each

    wmma::fragment<wmma::accumulator, 16, 16, 16, float> acc[4][4];
    #pragma unroll
    for (int i = 0; i < 4; i++)
        #pragma unroll
        for (int j = 0; j < 4; j++) wmma::fill_fragment(acc[i][j], 0.0f);

    auto load_stage = [&](int kt, int s) {
        __nv_bfloat16* base = sm + s * STAGE_ELEMS;
        __nv_bfloat16* sAh = base;
        __nv_bfloat16* sAl = base + A_ELEMS;
        __nv_bfloat16* sBh = base + 2 * A_ELEMS;
        __nv_bfloat16* sBl = base + 2 * A_ELEMS + B_ELEMS;
        int k0 = (kbase + kt) * GBK;
        // A tile: 256 rows x 32 cols, hi+lo. 1024 16B-chunks per plane.
        #pragma unroll
        for (int p = 0; p < 4; p++) {
            int idx = tid + p * 256;        // 0..1023
            int r = idx >> 2, cc = (idx & 3) * 8;
            size_t goff = (size_t)(m0 + r) * lda + k0 + cc;
            cpa16(sAh + r * ALD + cc, Agh + goff);
            cpa16(sAl + r * ALD + cc, Agl + goff);
        }
        // B tile: 32 rows x 128 cols, hi+lo. 512 16B-chunks per plane.
        #pragma unroll
        for (int p = 0; p < 2; p++) {
            int idx = tid + p * 256;        // 0..511
            int r = idx >> 4, cc = (idx & 15) * 8;
            size_t goff = (size_t)(k0 + r) * ldb + n0 + cc;
            cpa16(sBh + r * BLD + cc, Bgh + goff);
            cpa16(sBl + r * BLD + cc, Bgl + goff);
        }
        CP_COMMIT();
    };

    auto compute_stage = [&](int s) {
        __nv_bfloat16* base = sm + s * STAGE_ELEMS;
        __nv_bfloat16* sAh = base;
        __nv_bfloat16* sAl = base + A_ELEMS;
        __nv_bfloat16* sBh = base + 2 * A_ELEMS;
        __nv_bfloat16* sBl = base + 2 * A_ELEMS + B_ELEMS;
        #pragma unroll
        for (int kk = 0; kk < GBK; kk += 16) {
            // preload all B fragments for this warp's 64-col strip
            wmma::fragment<wmma::matrix_b, 16, 16, 16, __nv_bfloat16, wmma::row_major> bh[4], bl[4];
            #pragma unroll
            for (int j = 0; j < 4; j++) {
                wmma::load_matrix_sync(bh[j], sBh + kk * BLD + wn * 64 + j * 16, BLD);
                wmma::load_matrix_sync(bl[j], sBl + kk * BLD + wn * 64 + j * 16, BLD);
            }
            #pragma unroll
            for (int i = 0; i < 4; i++) {
                wmma::fragment<wmma::matrix_a, 16, 16, 16, __nv_bfloat16, wmma::row_major> ah, al;
                wmma::load_matrix_sync(ah, sAh + (wm * 64 + i * 16) * ALD + kk, ALD);
                wmma::load_matrix_sync(al, sAl + (wm * 64 + i * 16) * ALD + kk, ALD);
                #pragma unroll
                for (int j = 0; j < 4; j++) {
                    wmma::mma_sync(acc[i][j], ah, bh[j], acc[i][j]);
                    wmma::mma_sync(acc[i][j], ah, bl[j], acc[i][j]);
                    wmma::mma_sync(acc[i][j], al, bh[j], acc[i][j]);
                }
            }
        }
    };

    // prologue (2 stages)
    load_stage(0, 0);
    if (ktiles > 1) load_stage(1, 1);

    for (int kt = 0; kt < ktiles; kt++) {
        if (kt + 1 < ktiles) { CP_WAIT(1); } else { CP_WAIT(0); }
        __syncthreads();
        compute_stage(kt & 1);
        __syncthreads();
        if (kt + 2 < ktiles) load_stage(kt + 2, kt & 1);
    }

    #pragma unroll
    for (int i = 0; i < 4; i++)
        #pragma unroll
        for (int j = 0; j < 4; j++) {
            int gm = m0 + wm * 64 + i * 16;
            int gn = n0 + wn * 64 + j * 16;
            wmma::store_matrix_sync(&Cz[(size_t)gm * ldc + gn], acc[i][j], ldc, wmma::mem_row_major);
        }
}

// ---------------- depthwise causal conv(4) + SiLU (+ planar out) ----------------
__global__ void conv_silu_kernel(const float* __restrict__ cw,
                                 const float* __restrict__ cb)
{
    int idx = blockIdx.x * blockDim.x + threadIdx.x;   // over M_*DINNER
    int d = idx & (DINNER - 1);
    int m = idx >> 11;
    int l = m & (L_ - 1);
    int b = m >> 11;
    float acc = cb[d];
    #pragma unroll
    for (int w = 0; w < 4; w++) {
        int ll = l - 3 + w;
        if (ll >= 0)
            acc += g_xz[((size_t)(b * L_ + ll)) * 4096 + d] * cw[w * DINNER + d];
    }
    float v = acc / (1.0f + __expf(-acc));
    g_xconv[idx] = v;
    __nv_bfloat16 hh = __float2bfloat16(v);
    g_xc_h[idx] = hh;
    g_xc_l[idx] = __float2bfloat16(v - __bfloat162float(hh));
}

// ---------------- dt = softplus(dt_pre + b_dt) ----------------
__global__ void dt_softplus_kernel(const float* __restrict__ bdt)
{
    int idx = blockIdx.x * blockDim.x + threadIdx.x;
    int d = idx & (DINNER - 1);
    float v = g_dt[idx] + bdt[d];
    g_dt[idx] = (v > 20.0f) ? v : log1pf(__expf(v));
}

// ---------------- selective scan pass 1 ----------------
__global__ __launch_bounds__(256) void scan_pass1(const float* __restrict__ A_log)
{
    __shared__ float sBC[CHUNK][32];
    const int d = blockIdx.x * 256 + threadIdx.x;
    const int c = blockIdx.y;
    const int b = blockIdx.z;

    for (int i = threadIdx.x; i < CHUNK * 32; i += 256) {
        int r = i >> 5, q = i & 31;
        sBC[r][q] = g_proj[(size_t)(b * L_ + c * CHUNK + r) * 128 + 64 + q];
    }
    __syncthreads();

    float ac[DSTATE], P[DSTATE], h[DSTATE];
    #pragma unroll
    for (int s = 0; s < DSTATE; s++) {
        ac[s] = -expf(A_log[d * DSTATE + s]);
        P[s] = 1.0f;
        h[s] = 0.0f;
    }

    size_t base = (size_t)(b * L_ + c * CHUNK) * DINNER + d;
    for (int t = 0; t < CHUNK; t++) {
        float dtv = g_dt[base + (size_t)t * DINNER];
        float xv  = g_xconv[base + (size_t)t * DINNER];
        float dtx = dtv * xv;
        #pragma unroll
        for (int s = 0; s < DSTATE; s++) {
            float a = __expf(dtv * ac[s]);
            P[s] *= a;
            h[s] = a * h[s] + dtx * sBC[t][s];
        }
    }
    size_t o = ((size_t)(b * NCHUNK + c) * DSTATE) * DINNER + d;
    #pragma unroll
    for (int s = 0; s < DSTATE; s++) {
        g_cP[o + (size_t)s * DINNER] = P[s];
        g_cH[o + (size_t)s * DINNER] = h[s];
    }
}

// ---------------- pass 2: combine chunk states ----------------
__global__ void scan_pass2()
{
    int id = blockIdx.x * blockDim.x + threadIdx.x;    // B_*DINNER
    int b = id >> 11, d = id & (DINNER - 1);
    float h[DSTATE];
    #pragma unroll
    for (int s = 0; s < DSTATE; s++) h[s] = 0.0f;
    for (int c = 0; c < NCHUNK; c++) {
        size_t o = ((size_t)(b * NCHUNK + c) * DSTATE) * DINNER + d;
        #pragma unroll
        for (int s = 0; s < DSTATE; s++) {
            g_cH0[o + (size_t)s * DINNER] = h[s];
            h[s] = g_cP[o + (size_t)s * DINNER] * h[s] + g_cH[o + (size_t)s * DINNER];
        }
    }
}

// ---------------- pass 3: replay with true h0, emit y planes ----------------
__global__ __launch_bounds__(256) void scan_pass3(const float* __restrict__ A_log,
                                                  const float* __restrict__ Dvec)
{
    __shared__ float sBC[CHUNK][32];
    const int d = blockIdx.x * 256 + threadIdx.x;
    const int c = blockIdx.y;
    const int b = blockIdx.z;

    for (int i = threadIdx.x; i < CHUNK * 32; i += 256) {
        int r = i >> 5, q = i & 31;
        sBC[r][q] = g_proj[(size_t)(b * L_ + c * CHUNK + r) * 128 + 64 + q];
    }
    __syncthreads();

    float ac[DSTATE], h[DSTATE];
    size_t o = ((size_t)(b * NCHUNK + c) * DSTATE) * DINNER + d;
    #pragma unroll
    for (int s = 0; s < DSTATE; s++) {
        ac[s] = -expf(A_log[d * DSTATE + s]);
        h[s] = g_cH0[o + (size_t)s * DINNER];
    }
    float Dv = Dvec[d];

    size_t base = (size_t)(b * L_ + c * CHUNK) * DINNER + d;
    for (int t = 0; t < CHUNK; t++) {
        float dtv = g_dt[base + (size_t)t * DINNER];
        float xv  = g_xconv[base + (size_t)t * DINNER];
        float dtx = dtv * xv;
        float acc = 0.0f;
        #pragma unroll
        for (int s = 0; s < DSTATE; s++) {
            float a = __expf(dtv * ac[s]);
            h[s] = a * h[s] + dtx * sBC[t][s];
            acc += h[s] * sBC[t][16 + s];
        }
        acc += xv * Dv;
        float zv = g_xz[(size_t)(b * L_ + c * CHUNK + t) * 4096 + 2048 + d];
        acc *= zv / (1.0f + __expf(-zv));
        size_t oi = base + (size_t)t * DINNER;
        __nv_bfloat16 hh = __float2bfloat16(acc);
        g_y_h[oi] = hh;
        g_y_l[oi] = __float2bfloat16(acc - __bfloat162float(hh));
    }
}

// ---------------- launch ----------------
extern "C" void kernel_launch(void* const* d_in, const int* in_sizes, int n_in,
                              void* d_out, int out_size)
{
    const float* hs     = (const float*)d_in[0];
    const float* W_in   = (const float*)d_in[1];
    const float* conv_w = (const float*)d_in[2];
    const float* conv_b = (const float*)d_in[3];
    const float* W_x    = (const float*)d_in[4];
    const float* W_dt   = (const float*)d_in[5];
    const float* b_dt   = (const float*)d_in[6];
    const float* A_log  = (const float*)d_in[7];
    const float* Dvec   = (const float*)d_in[8];
    const float* W_out  = (const float*)d_in[9];
    float* out = (float*)d_out;

    cudaFuncSetAttribute(gemm_planar, cudaFuncAttributeMaxDynamicSharedMemorySize,
                         GEMM_SMEM_BYTES);

    float *xz, *proj, *dtb, *pk;
    __nv_bfloat16 *hs_h, *hs_l, *win_h, *win_l, *wdt_h, *wdt_l, *wout_h, *wout_l;
    __nv_bfloat16 *wx_h, *wx_l, *xc_h, *xc_l, *pj_h, *pj_l, *y_h, *y_l;
    cudaGetSymbolAddress((void**)&xz,    g_xz);
    cudaGetSymbolAddress((void**)&proj,  g_proj);
    cudaGetSymbolAddress((void**)&pk,    g_pk);
    cudaGetSymbolAddress((void**)&dtb,   g_dt);
    cudaGetSymbolAddress((void**)&hs_h,  g_hs_h);   cudaGetSymbolAddress((void**)&hs_l,  g_hs_l);
    cudaGetSymbolAddress((void**)&win_h, g_win_h);  cudaGetSymbolAddress((void**)&win_l, g_win_l);
    cudaGetSymbolAddress((void**)&wx_h,  g_wx_h);   cudaGetSymbolAddress((void**)&wx_l,  g_wx_l);
    cudaGetSymbolAddress((void**)&wdt_h, g_wdt_h);  cudaGetSymbolAddress((void**)&wdt_l, g_wdt_l);
    cudaGetSymbolAddress((void**)&wout_h,g_wout_h); cudaGetSymbolAddress((void**)&wout_l,g_wout_l);
    cudaGetSymbolAddress((void**)&xc_h,  g_xc_h);   cudaGetSymbolAddress((void**)&xc_l,  g_xc_l);
    cudaGetSymbolAddress((void**)&pj_h,  g_pj_h);   cudaGetSymbolAddress((void**)&pj_l,  g_pj_l);
    cudaGetSymbolAddress((void**)&y_h,   g_y_h);    cudaGetSymbolAddress((void**)&y_l,   g_y_l);

    // launches 1..3: converts needed by G1 (profiled slot appears to be launch #4)
    cvt_planar<<<(M_ * DMODEL) / 256, 256>>>(hs, hs_h, hs_l, M_ * DMODEL);
    cvt_planar<<<(DMODEL * 4096) / 256, 256>>>(W_in, win_h, win_l, DMODEL * 4096);
    cvt_wx<<<(DINNER * 128) / 256, 256>>>(W_x);

    // 4) G1: xz = hs @ W_in   (4096 x 4096 x 1024)
    gemm_planar<<<dim3(4096 / GBN, M_ / GBM), 256, GEMM_SMEM_BYTES>>>(
        hs_h, hs_l, DMODEL, win_h, win_l, 4096, xz, 4096, DMODEL / GBK, 0);

    // 5) depthwise conv + SiLU (+ planes)
    conv_silu_kernel<<<(M_ * DINNER) / 256, 256>>>(conv_w, conv_b);

    // 6) G3 split-K: pk[z] = xconv @ W_x over K-slice z   (4096 x 128 x 2048/8)
    gemm_planar<<<dim3(1, M_ / GBM, KSLICE), 256, GEMM_SMEM_BYTES>>>(
        xc_h, xc_l, DINNER, wx_h, wx_l, 128, pk, 128,
        (DINNER / GBK) / KSLICE, (size_t)M_ * 128);

    // 7) reduce partials -> proj
    reduce_proj<<<(M_ * 128) / 256, 256>>>();

    // 8) planar-ize proj
    cvt_planar<<<(M_ * 128) / 256, 256>>>(proj, pj_h, pj_l, M_ * 128);

    // 9) convert W_dt
    cvt_planar<<<(DTRANK * DINNER) / 256, 256>>>(W_dt, wdt_h, wdt_l, DTRANK * DINNER);

    // 10) G4: dt_pre = proj[:, :64] @ W_dt   (4096 x 2048 x 64)
    gemm_planar<<<dim3(DINNER / GBN, M_ / GBM), 256, GEMM_SMEM_BYTES>>>(
        pj_h, pj_l, 128, wdt_h, wdt_l, DINNER, dtb, DINNER, DTRANK / GBK, 0);

    // 11) dt = softplus(dt_pre + b_dt)
    dt_softplus_kernel<<<(M_ * DINNER) / 256, 256>>>(b_dt);

    // 12-14) selective scan
    scan_pass1<<<dim3(DINNER / 256, NCHUNK, B_), 256>>>(A_log);
    scan_pass2<<<(B_ * DINNER) / 256, 256>>>();
    scan_pass3<<<dim3(DINNER / 256, NCHUNK, B_), 256>>>(A_log, Dvec);

    // 15) convert W_out
    cvt_planar<<<(DINNER * DMODEL) / 256, 256>>>(W_out, wout_h, wout_l, DINNER * DMODEL);

    // 16) G7: out = y @ W_out   (4096 x 1024 x 2048)
    gemm_planar<<<dim3(DMODEL / GBN, M_ / GBM), 256, GEMM_SMEM_BYTES>>>(
        y_h, y_l, DINNER, wout_h, wout_l, DMODEL, out, DMODEL, DINNER / GBK, 0);
}